// round 1
// baseline (speedup 1.0000x reference)
#include <cuda_runtime.h>

#define E_NODES 1000000
#define NH 64

// Scratch activations (alloc-free rule: __device__ globals)
__device__ float g_bufA[(size_t)E_NODES * NH];
__device__ float g_bufB[(size_t)E_NODES * NH];

// ---------------------------------------------------------------------------
// One fused mesh-conv layer:
//   feats = [x, |a-c|, a+c, |b-d|, b+d]  (K = 5*C)
//   h = feats @ W + bias ; y = relu(LN(h)) [+ x residual]
//   if CLS: logits = relu(y @ cw1 + cb1) @ cw2 + cb2  -> out[node] (float)
//   else:   out[node*64 + :] = y
// Tile: 128 nodes x 64 outputs per 256-thread block.
// ---------------------------------------------------------------------------
template <int C, bool RESID, bool CLS>
__global__ __launch_bounds__(256)
void mesh_layer_kernel(const float* __restrict__ xin,
                       const int*   __restrict__ nbr,
                       const float* __restrict__ W,
                       const float* __restrict__ bias,
                       const float* __restrict__ lng,
                       const float* __restrict__ lnb,
                       const float* __restrict__ cw1,
                       const float* __restrict__ cb1,
                       const float* __restrict__ cw2,
                       const float* __restrict__ cb2,
                       float* __restrict__ out)
{
    constexpr int K5  = 5 * C;
    constexpr int NP  = 132;                       // padded node stride in sF
    constexpr int FSZ = (2 * C * NP > 128 * 65) ? (2 * C * NP) : (128 * 65);

    extern __shared__ float sm[];
    float* sW    = sm;                  // K5 * 64
    float* sF    = sW + K5 * 64;        // FSZ  (feats segment / C-tile reuse)
    float* sLNg  = sF + FSZ;            // 64
    float* sLNb  = sLNg + 64;           // 64
    float* sBias = sLNb + 64;           // 64
    int*   sIdx  = (int*)(sBias + 64);  // 512 ints (128 x int4)
    float* sC1   = (float*)(sIdx + 512);// 64*32
    float* sB1   = sC1 + 64 * 32;       // 32
    float* sC2   = sB1 + 32;            // 32

    const int tid   = threadIdx.x;
    const int node0 = blockIdx.x * 128;

    // ---- stage W, LN params, neighbor indices, classifier weights ----
    for (int i = tid; i < K5 * 16; i += 256)            // K5*64/4 float4s
        ((float4*)sW)[i] = ((const float4*)W)[i];
    if (tid < 64) {
        sLNg[tid]  = lng[tid];
        sLNb[tid]  = lnb[tid];
        sBias[tid] = bias[tid];
    }
    if (tid < 128) {
        int node = node0 + tid;
        int4 v = (node < E_NODES) ? ((const int4*)nbr)[node] : make_int4(0, 0, 0, 0);
        ((int4*)sIdx)[tid] = v;
    }
    if (CLS) {
        for (int i = tid; i < 64 * 32 / 4; i += 256)
            ((float4*)sC1)[i] = ((const float4*)cw1)[i];
        if (tid < 32) { sB1[tid] = cb1[tid]; sC2[tid] = cw2[tid]; }
    }
    __syncthreads();

    const int tr = tid >> 4;     // 0..15 -> rows tr*8 .. tr*8+7
    const int tc = tid & 15;     // 0..15 -> cols tc*4 .. tc*4+3

    float acc[8][4];
#pragma unroll
    for (int r = 0; r < 8; r++)
#pragma unroll
        for (int c = 0; c < 4; c++) acc[r][c] = 0.f;

    // gather-thread mapping: 2 threads per node (half rows)
    const int  n      = tid >> 1;
    const int  half   = tid & 1;
    const int  nodeL  = node0 + n;
    const bool validL = (nodeL < E_NODES);

    for (int ph = 0; ph < 3; ph++) {
        // ---------- gather + transpose feats segment into sF[k][node] ----------
        if (ph == 0) {
            if (validL) {
                if (C == 64) {
                    const float4* xr = (const float4*)(xin + (size_t)nodeL * 64) + half * 8;
#pragma unroll
                    for (int i = 0; i < 8; i++) {
                        float4 v = xr[i];
                        int ch = half * 32 + i * 4;
                        sF[(ch + 0) * NP + n] = v.x;
                        sF[(ch + 1) * NP + n] = v.y;
                        sF[(ch + 2) * NP + n] = v.z;
                        sF[(ch + 3) * NP + n] = v.w;
                    }
                } else {
                    int lo = half ? (C + 1) / 2 : 0;
                    int hi = half ? C : (C + 1) / 2;
                    for (int ch = lo; ch < hi; ch++)
                        sF[ch * NP + n] = xin[(size_t)nodeL * C + ch];
                }
            }
        } else {
            const int ia = sIdx[4 * n + (ph == 1 ? 0 : 1)];
            const int ic = sIdx[4 * n + (ph == 1 ? 2 : 3)];
            if (validL) {
                if (C == 64) {
                    const float4* ar = (const float4*)(xin + (size_t)ia * 64) + half * 8;
                    const float4* cr = (const float4*)(xin + (size_t)ic * 64) + half * 8;
#pragma unroll
                    for (int i = 0; i < 8; i++) {
                        float4 a = ar[i], c = cr[i];
                        int ch = half * 32 + i * 4;
                        sF[(ch + 0) * NP + n]     = fabsf(a.x - c.x);
                        sF[(C + ch + 0) * NP + n] = a.x + c.x;
                        sF[(ch + 1) * NP + n]     = fabsf(a.y - c.y);
                        sF[(C + ch + 1) * NP + n] = a.y + c.y;
                        sF[(ch + 2) * NP + n]     = fabsf(a.z - c.z);
                        sF[(C + ch + 2) * NP + n] = a.z + c.z;
                        sF[(ch + 3) * NP + n]     = fabsf(a.w - c.w);
                        sF[(C + ch + 3) * NP + n] = a.w + c.w;
                    }
                } else {
                    int lo = half ? (C + 1) / 2 : 0;
                    int hi = half ? C : (C + 1) / 2;
                    for (int ch = lo; ch < hi; ch++) {
                        float a = xin[(size_t)ia * C + ch];
                        float c = xin[(size_t)ic * C + ch];
                        sF[ch * NP + n]       = fabsf(a - c);
                        sF[(C + ch) * NP + n] = a + c;
                    }
                }
            }
        }
        __syncthreads();

        // ---------- GEMM over this K segment ----------
        const int Kc = (ph == 0) ? C : 2 * C;
        const int k0 = (ph == 0) ? 0 : (ph == 1 ? C : 3 * C);
#pragma unroll 2
        for (int k = 0; k < Kc; k++) {
            const float4* fp = (const float4*)(sF + k * NP + tr * 8);
            float4 f0 = fp[0];
            float4 f1 = fp[1];
            float4 w  = ((const float4*)(sW + (k0 + k) * 64))[tc];
            float fr[8] = {f0.x, f0.y, f0.z, f0.w, f1.x, f1.y, f1.z, f1.w};
#pragma unroll
            for (int r = 0; r < 8; r++) {
                acc[r][0] += fr[r] * w.x;
                acc[r][1] += fr[r] * w.y;
                acc[r][2] += fr[r] * w.z;
                acc[r][3] += fr[r] * w.w;
            }
        }
        __syncthreads();
    }

    // ---------- stage C tile into smem (row stride 65 to kill conflicts) ----------
    float* sC = sF;
#pragma unroll
    for (int r = 0; r < 8; r++)
#pragma unroll
        for (int c = 0; c < 4; c++)
            sC[(tr * 8 + r) * 65 + tc * 4 + c] = acc[r][c];
    __syncthreads();

    // ---------- bias + LayerNorm + ReLU (one thread per row) ----------
    if (tid < 128 && (node0 + tid) < E_NODES) {
        const int row = tid;
        float mu = 0.f;
        for (int i = 0; i < 64; i++) mu += sC[row * 65 + i] + sBias[i];
        mu *= (1.f / 64.f);
        float var = 0.f;
        for (int i = 0; i < 64; i++) {
            float d = sC[row * 65 + i] + sBias[i] - mu;
            var += d * d;
        }
        var *= (1.f / 64.f);
        float rs = rsqrtf(var + 1e-5f);
        for (int i = 0; i < 64; i++) {
            float y = (sC[row * 65 + i] + sBias[i] - mu) * rs * sLNg[i] + sLNb[i];
            sC[row * 65 + i] = fmaxf(y, 0.f);
        }
    }
    __syncthreads();

    if (!CLS) {
        // residual + coalesced store (2 threads per node, float4)
        if (validL) {
            float4* orow = (float4*)(out + (size_t)nodeL * 64) + half * 8;
            const float4* xr = RESID ? ((const float4*)(xin + (size_t)nodeL * 64) + half * 8)
                                     : (const float4*)0;
#pragma unroll
            for (int i = 0; i < 8; i++) {
                int c0 = half * 32 + i * 4;
                float4 r;
                r.x = sC[n * 65 + c0 + 0];
                r.y = sC[n * 65 + c0 + 1];
                r.z = sC[n * 65 + c0 + 2];
                r.w = sC[n * 65 + c0 + 3];
                if (RESID) {
                    float4 x4 = xr[i];
                    r.x += x4.x; r.y += x4.y; r.z += x4.z; r.w += x4.w;
                }
                orow[i] = r;
            }
        }
    } else {
        // residual add into smem, then fused classifier head
        if (RESID && validL) {
            const float4* xr = (const float4*)(xin + (size_t)nodeL * 64) + half * 8;
#pragma unroll
            for (int i = 0; i < 8; i++) {
                float4 x4 = xr[i];
                int c0 = half * 32 + i * 4;
                sC[n * 65 + c0 + 0] += x4.x;
                sC[n * 65 + c0 + 1] += x4.y;
                sC[n * 65 + c0 + 2] += x4.z;
                sC[n * 65 + c0 + 3] += x4.w;
            }
        }
        __syncthreads();
        if (tid < 128 && (node0 + tid) < E_NODES) {
            const int row = tid;
            float z[32];
#pragma unroll
            for (int j = 0; j < 32; j++) z[j] = sB1[j];
            for (int i = 0; i < 64; i++) {
                float vi = sC[row * 65 + i];
                const float4* wr = (const float4*)(sC1 + i * 32);
#pragma unroll
                for (int j4 = 0; j4 < 8; j4++) {
                    float4 w4 = wr[j4];
                    z[4 * j4 + 0] += vi * w4.x;
                    z[4 * j4 + 1] += vi * w4.y;
                    z[4 * j4 + 2] += vi * w4.z;
                    z[4 * j4 + 3] += vi * w4.w;
                }
            }
            float logit = cb2[0];
#pragma unroll
            for (int j = 0; j < 32; j++) logit += fmaxf(z[j], 0.f) * sC2[j];
            out[node0 + row] = logit;
        }
    }
}

// ---------------------------------------------------------------------------

static size_t smem_bytes_for(int C)
{
    int K5  = 5 * C;
    int NP  = 132;
    int FSZ = (2 * C * NP > 128 * 65) ? 2 * C * NP : 128 * 65;
    // sW + sF + (g,b,bias) + idx(512 int) + cw1 + cb1 + cw2
    return (size_t)(K5 * 64 + FSZ + 64 * 3 + 512 + 64 * 32 + 32 + 32) * 4;
}

extern "C" void kernel_launch(void* const* d_in, const int* in_sizes, int n_in,
                              void* d_out, int out_size)
{
    const float* x      = (const float*)d_in[0];
    const int*   nbr    = (const int*)  d_in[1];
    const float* w0     = (const float*)d_in[2];
    const float* b0     = (const float*)d_in[3];
    const float* w_rest = (const float*)d_in[4];
    const float* b_rest = (const float*)d_in[5];
    const float* ln_g   = (const float*)d_in[6];
    const float* ln_b   = (const float*)d_in[7];
    const float* cw1    = (const float*)d_in[8];
    const float* cb1    = (const float*)d_in[9];
    const float* cw2    = (const float*)d_in[10];
    const float* cb2    = (const float*)d_in[11];
    float* out = (float*)d_out;

    float *bufA, *bufB;
    cudaGetSymbolAddress((void**)&bufA, g_bufA);
    cudaGetSymbolAddress((void**)&bufB, g_bufB);

    const size_t s11 = smem_bytes_for(11);
    const size_t s64 = smem_bytes_for(64);

    cudaFuncSetAttribute(mesh_layer_kernel<11, false, false>,
                         cudaFuncAttributeMaxDynamicSharedMemorySize, (int)s11);
    cudaFuncSetAttribute(mesh_layer_kernel<64, true, false>,
                         cudaFuncAttributeMaxDynamicSharedMemorySize, (int)s64);
    cudaFuncSetAttribute(mesh_layer_kernel<64, true, true>,
                         cudaFuncAttributeMaxDynamicSharedMemorySize, (int)s64);

    dim3 grid((E_NODES + 127) / 128);
    dim3 block(256);

    // Layer 0: C=11, no residual
    mesh_layer_kernel<11, false, false><<<grid, block, s11>>>(
        x, nbr, w0, b0, ln_g, ln_b,
        nullptr, nullptr, nullptr, nullptr, bufA);

    // Layer 1
    mesh_layer_kernel<64, true, false><<<grid, block, s64>>>(
        bufA, nbr, w_rest, b_rest, ln_g + 64, ln_b + 64,
        nullptr, nullptr, nullptr, nullptr, bufB);

    // Layer 2
    mesh_layer_kernel<64, true, false><<<grid, block, s64>>>(
        bufB, nbr, w_rest + 320 * 64, b_rest + 64, ln_g + 128, ln_b + 128,
        nullptr, nullptr, nullptr, nullptr, bufA);

    // Layer 3 + fused classifier head -> logits
    mesh_layer_kernel<64, true, true><<<grid, block, s64>>>(
        bufA, nbr, w_rest + 2 * 320 * 64, b_rest + 128, ln_g + 192, ln_b + 192,
        cw1, cb1, cw2, cb2, out);
}

// round 2
// speedup vs baseline: 1.1325x; 1.1325x over previous
#include <cuda_runtime.h>

#define E_NODES 1000000
#define NH 64

typedef unsigned long long u64;

// Scratch activations (alloc-free rule: __device__ globals)
__device__ float g_bufA[(size_t)E_NODES * NH];
__device__ float g_bufB[(size_t)E_NODES * NH];

__device__ __forceinline__ u64 pk2(float lo, float hi) {
    u64 r; asm("mov.b64 %0,{%1,%2};" : "=l"(r) : "f"(lo), "f"(hi)); return r;
}
__device__ __forceinline__ void upk2(u64 v, float& lo, float& hi) {
    asm("mov.b64 {%0,%1},%2;" : "=f"(lo), "=f"(hi) : "l"(v));
}
__device__ __forceinline__ void ffma2(u64& d, u64 a, u64 b) {
    asm("fma.rn.f32x2 %0,%1,%2,%0;" : "+l"(d) : "l"(a), "l"(b));
}

// ---------------------------------------------------------------------------
// One fused mesh-conv layer:
//   feats = [x, |a-c|, a+c, |b-d|, b+d]  (K = 5*C)
//   h = feats @ W + bias ; y = relu(LN(h)) [+ x residual]
//   if CLS: logits = relu(y @ cw1 + cb1) @ cw2 + cb2  -> out[node]
// Tile: 128 nodes x 64 outputs per 256-thread block, 2 blocks/SM.
// K processed in 3 phases (x | a,c pair | b,d pair); per-phase W chunk staged.
// ---------------------------------------------------------------------------
template <int C, bool RESID, bool CLS>
__global__ __launch_bounds__(256, 2)
void mesh_layer_kernel(const float* __restrict__ xin,
                       const int*   __restrict__ nbr,
                       const float* __restrict__ W,
                       const float* __restrict__ bias,
                       const float* __restrict__ lng,
                       const float* __restrict__ lnb,
                       const float* __restrict__ cw1,
                       const float* __restrict__ cb1,
                       const float* __restrict__ cw2,
                       const float* __restrict__ cb2,
                       float* __restrict__ out)
{
    constexpr int NP  = 128;                               // node stride in sF
    constexpr int FSZ = (2 * C * NP > 128 * 65) ? (2 * C * NP) : (128 * 65);
    constexpr int WSZ = 2 * C * 64;                        // max phase chunk

    extern __shared__ float sm[];
    float* sW    = sm;                   // WSZ  (current K-chunk of W)
    float* sF    = sW + WSZ;             // FSZ  (feats chunk / C-tile reuse)
    float* sLNg  = sF + FSZ;             // 64
    float* sLNb  = sLNg + 64;            // 64
    float* sBias = sLNb + 64;            // 64
    int*   sIdx  = (int*)(sBias + 64);   // 512 ints (128 x int4)
    float* sC1   = (float*)(sIdx + 512); // 64*32   (CLS only)
    float* sB1   = sC1 + 64 * 32;        // 32
    float* sC2   = sB1 + 32;             // 32

    const int tid   = threadIdx.x;
    const int node0 = blockIdx.x * 128;

    if (tid < 64) {
        sLNg[tid]  = lng[tid];
        sLNb[tid]  = lnb[tid];
        sBias[tid] = bias[tid];
    }
    if (tid < 128) {
        int node = node0 + tid;
        int4 v = (node < E_NODES) ? ((const int4*)nbr)[node] : make_int4(0, 0, 0, 0);
        ((int4*)sIdx)[tid] = v;
    }
    if (CLS) {
        for (int i = tid; i < 64 * 32 / 4; i += 256)
            ((float4*)sC1)[i] = ((const float4*)cw1)[i];
        if (tid < 32) { sB1[tid] = cb1[tid]; sC2[tid] = cw2[tid]; }
    }

    const int tr = tid >> 4;     // 0..15 -> rows tr*8 .. tr*8+7
    const int tc = tid & 15;     // 0..15 -> cols tc*4 .. tc*4+3

    u64 acc2[4][4];              // 4 row-pairs x 4 cols, packed f32x2
#pragma unroll
    for (int r = 0; r < 4; r++)
#pragma unroll
        for (int c = 0; c < 4; c++) acc2[r][c] = 0ull;

    // gather mapping: 2 threads per node (half rows)
    const int  n      = tid >> 1;
    const int  half   = tid & 1;
    const int  nodeL  = node0 + n;
    const bool validL = (nodeL < E_NODES);

    // first sync covers sIdx before phase-1 reads (phase 0 doesn't need it)
    __syncthreads();

    for (int ph = 0; ph < 3; ph++) {
        const int Kc = (ph == 0) ? C : 2 * C;
        const int k0 = (ph == 0) ? 0 : (ph == 1 ? C : 3 * C);

        // ---- stage W chunk for this phase ----
        for (int i = tid; i < Kc * 16; i += 256)
            ((float4*)sW)[i] = ((const float4*)(W + (size_t)k0 * 64))[i];

        // ---- gather + transpose feats chunk into sF[k][node] ----
        if (ph == 0) {
            if (validL) {
                if (C == 64) {
                    const float4* xr = (const float4*)(xin + (size_t)nodeL * 64) + half * 8;
#pragma unroll
                    for (int i = 0; i < 8; i++) {
                        float4 v = xr[i];
                        int ch = half * 32 + i * 4;
                        sF[(ch + 0) * NP + n] = v.x;
                        sF[(ch + 1) * NP + n] = v.y;
                        sF[(ch + 2) * NP + n] = v.z;
                        sF[(ch + 3) * NP + n] = v.w;
                    }
                } else {
                    int lo = half ? (C + 1) / 2 : 0;
                    int hi = half ? C : (C + 1) / 2;
                    for (int ch = lo; ch < hi; ch++)
                        sF[ch * NP + n] = xin[(size_t)nodeL * C + ch];
                }
            }
        } else {
            const int ia = sIdx[4 * n + (ph == 1 ? 0 : 1)];
            const int ic = sIdx[4 * n + (ph == 1 ? 2 : 3)];
            if (validL) {
                if (C == 64) {
                    const float4* ar = (const float4*)(xin + (size_t)ia * 64) + half * 8;
                    const float4* cr = (const float4*)(xin + (size_t)ic * 64) + half * 8;
#pragma unroll
                    for (int i = 0; i < 8; i++) {
                        float4 a = ar[i], c = cr[i];
                        int ch = half * 32 + i * 4;
                        sF[(ch + 0) * NP + n]     = fabsf(a.x - c.x);
                        sF[(C + ch + 0) * NP + n] = a.x + c.x;
                        sF[(ch + 1) * NP + n]     = fabsf(a.y - c.y);
                        sF[(C + ch + 1) * NP + n] = a.y + c.y;
                        sF[(ch + 2) * NP + n]     = fabsf(a.z - c.z);
                        sF[(C + ch + 2) * NP + n] = a.z + c.z;
                        sF[(ch + 3) * NP + n]     = fabsf(a.w - c.w);
                        sF[(C + ch + 3) * NP + n] = a.w + c.w;
                    }
                } else {
                    int lo = half ? (C + 1) / 2 : 0;
                    int hi = half ? C : (C + 1) / 2;
                    for (int ch = lo; ch < hi; ch++) {
                        float a = xin[(size_t)ia * C + ch];
                        float c = xin[(size_t)ic * C + ch];
                        sF[ch * NP + n]       = fabsf(a - c);
                        sF[(C + ch) * NP + n] = a + c;
                    }
                }
            }
        }
        __syncthreads();

        // ---- GEMM over this K chunk (packed f32x2 FMA) ----
#pragma unroll 2
        for (int k = 0; k < Kc; k++) {
            const u64* fp = (const u64*)(sF + k * NP + tr * 8);
            u64 f0 = fp[0], f1 = fp[1], f2v = fp[2], f3 = fp[3];
            float4 w = ((const float4*)(sW + k * 64))[tc];
            u64 w0 = pk2(w.x, w.x);
            u64 w1 = pk2(w.y, w.y);
            u64 w2 = pk2(w.z, w.z);
            u64 w3 = pk2(w.w, w.w);
            ffma2(acc2[0][0], f0, w0); ffma2(acc2[0][1], f0, w1);
            ffma2(acc2[0][2], f0, w2); ffma2(acc2[0][3], f0, w3);
            ffma2(acc2[1][0], f1, w0); ffma2(acc2[1][1], f1, w1);
            ffma2(acc2[1][2], f1, w2); ffma2(acc2[1][3], f1, w3);
            ffma2(acc2[2][0], f2v, w0); ffma2(acc2[2][1], f2v, w1);
            ffma2(acc2[2][2], f2v, w2); ffma2(acc2[2][3], f2v, w3);
            ffma2(acc2[3][0], f3, w0); ffma2(acc2[3][1], f3, w1);
            ffma2(acc2[3][2], f3, w2); ffma2(acc2[3][3], f3, w3);
        }
        __syncthreads();
    }

    // ---- stage C tile into smem (row stride 65 kills conflicts) ----
    float* sC = sF;
#pragma unroll
    for (int rp = 0; rp < 4; rp++)
#pragma unroll
        for (int c = 0; c < 4; c++) {
            float lo, hi;
            upk2(acc2[rp][c], lo, hi);
            sC[(tr * 8 + 2 * rp + 0) * 65 + tc * 4 + c] = lo;
            sC[(tr * 8 + 2 * rp + 1) * 65 + tc * 4 + c] = hi;
        }
    __syncthreads();

    // ---- bias + LayerNorm + ReLU (one thread per node row) ----
    if (tid < 128 && (node0 + tid) < E_NODES) {
        const int row = tid;
        float mu = 0.f;
        for (int i = 0; i < 64; i++) mu += sC[row * 65 + i] + sBias[i];
        mu *= (1.f / 64.f);
        float var = 0.f;
        for (int i = 0; i < 64; i++) {
            float d = sC[row * 65 + i] + sBias[i] - mu;
            var += d * d;
        }
        var *= (1.f / 64.f);
        float rs = rsqrtf(var + 1e-5f);
        for (int i = 0; i < 64; i++) {
            float y = (sC[row * 65 + i] + sBias[i] - mu) * rs * sLNg[i] + sLNb[i];
            sC[row * 65 + i] = fmaxf(y, 0.f);
        }
    }
    __syncthreads();

    if (!CLS) {
        // residual + coalesced store (2 threads per node, float4)
        if (validL) {
            float4* orow = (float4*)(out + (size_t)nodeL * 64) + half * 8;
            const float4* xr = RESID ? ((const float4*)(xin + (size_t)nodeL * 64) + half * 8)
                                     : (const float4*)0;
#pragma unroll
            for (int i = 0; i < 8; i++) {
                int c0 = half * 32 + i * 4;
                float4 r;
                r.x = sC[n * 65 + c0 + 0];
                r.y = sC[n * 65 + c0 + 1];
                r.z = sC[n * 65 + c0 + 2];
                r.w = sC[n * 65 + c0 + 3];
                if (RESID) {
                    float4 x4 = xr[i];
                    r.x += x4.x; r.y += x4.y; r.z += x4.z; r.w += x4.w;
                }
                orow[i] = r;
            }
        }
    } else {
        // residual add into smem, then fused classifier head
        if (RESID && validL) {
            const float4* xr = (const float4*)(xin + (size_t)nodeL * 64) + half * 8;
#pragma unroll
            for (int i = 0; i < 8; i++) {
                float4 x4 = xr[i];
                int c0 = half * 32 + i * 4;
                sC[n * 65 + c0 + 0] += x4.x;
                sC[n * 65 + c0 + 1] += x4.y;
                sC[n * 65 + c0 + 2] += x4.z;
                sC[n * 65 + c0 + 3] += x4.w;
            }
        }
        __syncthreads();
        if (tid < 128 && (node0 + tid) < E_NODES) {
            const int row = tid;
            float z[32];
#pragma unroll
            for (int j = 0; j < 32; j++) z[j] = sB1[j];
            for (int i = 0; i < 64; i++) {
                float vi = sC[row * 65 + i];
                const float4* wr = (const float4*)(sC1 + i * 32);
#pragma unroll
                for (int j4 = 0; j4 < 8; j4++) {
                    float4 w4 = wr[j4];
                    z[4 * j4 + 0] += vi * w4.x;
                    z[4 * j4 + 1] += vi * w4.y;
                    z[4 * j4 + 2] += vi * w4.z;
                    z[4 * j4 + 3] += vi * w4.w;
                }
            }
            float logit = cb2[0];
#pragma unroll
            for (int j = 0; j < 32; j++) logit += fmaxf(z[j], 0.f) * sC2[j];
            out[node0 + row] = logit;
        }
    }
}

// ---------------------------------------------------------------------------

static size_t smem_bytes_for(int C, bool cls)
{
    int NP  = 128;
    int FSZ = (2 * C * NP > 128 * 65) ? 2 * C * NP : 128 * 65;
    size_t f = (size_t)(2 * C * 64) + FSZ + 64 * 3 + 512 + (cls ? (64 * 32 + 64) : 0);
    return f * 4;
}

extern "C" void kernel_launch(void* const* d_in, const int* in_sizes, int n_in,
                              void* d_out, int out_size)
{
    const float* x      = (const float*)d_in[0];
    const int*   nbr    = (const int*)  d_in[1];
    const float* w0     = (const float*)d_in[2];
    const float* b0     = (const float*)d_in[3];
    const float* w_rest = (const float*)d_in[4];
    const float* b_rest = (const float*)d_in[5];
    const float* ln_g   = (const float*)d_in[6];
    const float* ln_b   = (const float*)d_in[7];
    const float* cw1    = (const float*)d_in[8];
    const float* cb1    = (const float*)d_in[9];
    const float* cw2    = (const float*)d_in[10];
    const float* cb2    = (const float*)d_in[11];
    float* out = (float*)d_out;

    float *bufA, *bufB;
    cudaGetSymbolAddress((void**)&bufA, g_bufA);
    cudaGetSymbolAddress((void**)&bufB, g_bufB);

    const size_t s11 = smem_bytes_for(11, false);
    const size_t s64 = smem_bytes_for(64, false);
    const size_t s64c = smem_bytes_for(64, true);

    cudaFuncSetAttribute(mesh_layer_kernel<11, false, false>,
                         cudaFuncAttributeMaxDynamicSharedMemorySize, (int)s11);
    cudaFuncSetAttribute(mesh_layer_kernel<64, true, false>,
                         cudaFuncAttributeMaxDynamicSharedMemorySize, (int)s64);
    cudaFuncSetAttribute(mesh_layer_kernel<64, true, true>,
                         cudaFuncAttributeMaxDynamicSharedMemorySize, (int)s64c);

    dim3 grid((E_NODES + 127) / 128);
    dim3 block(256);

    // Layer 0: C=11, no residual
    mesh_layer_kernel<11, false, false><<<grid, block, s11>>>(
        x, nbr, w0, b0, ln_g, ln_b,
        nullptr, nullptr, nullptr, nullptr, bufA);

    // Layer 1
    mesh_layer_kernel<64, true, false><<<grid, block, s64>>>(
        bufA, nbr, w_rest, b_rest, ln_g + 64, ln_b + 64,
        nullptr, nullptr, nullptr, nullptr, bufB);

    // Layer 2
    mesh_layer_kernel<64, true, false><<<grid, block, s64>>>(
        bufB, nbr, w_rest + 320 * 64, b_rest + 64, ln_g + 128, ln_b + 128,
        nullptr, nullptr, nullptr, nullptr, bufA);

    // Layer 3 + fused classifier head -> logits
    mesh_layer_kernel<64, true, true><<<grid, block, s64c>>>(
        bufA, nbr, w_rest + 2 * 320 * 64, b_rest + 128, ln_g + 192, ln_b + 192,
        cw1, cb1, cw2, cb2, out);
}

// round 5
// speedup vs baseline: 1.5181x; 1.3405x over previous
#include <cuda_runtime.h>
#include <cuda_bf16.h>
#include <cstdint>

typedef unsigned int u32;
typedef unsigned long long u64;

#define E_NODES 1000000

// Scratch activations + pre-split weights (alloc-free rule: __device__ globals)
__device__ float g_bufA[(size_t)E_NODES * 64];
__device__ float g_bufB[(size_t)E_NODES * 64];
__device__ __nv_bfloat16 g_W0[2 * 64 * 64];      // layer0: [term][n][kpad64]
__device__ __nv_bfloat16 g_WR[3 * 2 * 64 * 320]; // layers1-3: [l][term][n][k]

// ---------------------------------------------------------------------------
// helpers
// ---------------------------------------------------------------------------
__device__ __forceinline__ u32 s2u(const void* p) {
    u32 a;
    asm("{.reg .u64 t; cvta.to.shared.u64 t,%1; cvt.u32.u64 %0,t;}" : "=r"(a) : "l"(p));
    return a;
}
__device__ __forceinline__ u32 swz(u32 b) { return b ^ ((b >> 3) & 0x70); }

__device__ __forceinline__ void ldmx4(u32* r, u32 addr) {
    asm volatile("ldmatrix.sync.aligned.m8n8.x4.shared.b16 {%0,%1,%2,%3},[%4];"
                 : "=r"(r[0]), "=r"(r[1]), "=r"(r[2]), "=r"(r[3]) : "r"(addr));
}
__device__ __forceinline__ void mma16816(float* d, const u32* a, u32 b0, u32 b1) {
    asm volatile(
        "mma.sync.aligned.m16n8k16.row.col.f32.bf16.bf16.f32 "
        "{%0,%1,%2,%3},{%4,%5,%6,%7},{%8,%9},{%0,%1,%2,%3};"
        : "+f"(d[0]), "+f"(d[1]), "+f"(d[2]), "+f"(d[3])
        : "r"(a[0]), "r"(a[1]), "r"(a[2]), "r"(a[3]), "r"(b0), "r"(b1));
}

__device__ __forceinline__ u64 pk2(float lo, float hi) {
    u64 r; asm("mov.b64 %0,{%1,%2};" : "=l"(r) : "f"(lo), "f"(hi)); return r;
}
__device__ __forceinline__ void upk2(u64 v, float& lo, float& hi) {
    asm("mov.b64 {%0,%1},%2;" : "=f"(lo), "=f"(hi) : "l"(v));
}
__device__ __forceinline__ void ffma2(u64& d, u64 a, u64 b) {
    asm("fma.rn.f32x2 %0,%1,%2,%0;" : "+l"(d) : "l"(a), "l"(b));
}

__device__ __forceinline__ u32 bits2(__nv_bfloat162 v) {
    u32 u; __builtin_memcpy(&u, &v, 4); return u;
}
// write 4 consecutive k-cols of one A row, split hi/lo
__device__ __forceinline__ void wr4(char* hT, char* lT, int n, int kc,
                                    float v0, float v1, float v2, float v3) {
    __nv_bfloat162 h01 = __floats2bfloat162_rn(v0, v1);
    __nv_bfloat162 h23 = __floats2bfloat162_rn(v2, v3);
    __nv_bfloat162 l01 = __floats2bfloat162_rn(v0 - __bfloat162float(h01.x),
                                               v1 - __bfloat162float(h01.y));
    __nv_bfloat162 l23 = __floats2bfloat162_rn(v2 - __bfloat162float(h23.x),
                                               v3 - __bfloat162float(h23.y));
    u32 off = swz((u32)(n * 128 + kc * 2));
    *(uint2*)(hT + off) = make_uint2(bits2(h01), bits2(h23));
    *(uint2*)(lT + off) = make_uint2(bits2(l01), bits2(l23));
}
__device__ __forceinline__ void wr1(char* hT, char* lT, int n, int k, float v) {
    __nv_bfloat16 h = __float2bfloat16_rn(v);
    __nv_bfloat16 l = __float2bfloat16_rn(v - __bfloat162float(h));
    u32 off = swz((u32)(n * 128 + k * 2));
    *(__nv_bfloat16*)(hT + off) = h;
    *(__nv_bfloat16*)(lT + off) = l;
}

// ---------------------------------------------------------------------------
// weight prep: transpose to [n][k], split bf16 hi/lo, zero-pad layer0 K 55->64
// ---------------------------------------------------------------------------
__global__ void prep_w(const float* __restrict__ w0, const float* __restrict__ wr)
{
    int i = blockIdx.x * blockDim.x + threadIdx.x;
    if (i < 64 * 64) {
        int n = i >> 6, k = i & 63;
        float v = (k < 55) ? w0[k * 64 + n] : 0.f;
        __nv_bfloat16 h = __float2bfloat16_rn(v);
        g_W0[(0 * 64 + n) * 64 + k] = h;
        g_W0[(1 * 64 + n) * 64 + k] = __float2bfloat16_rn(v - __bfloat162float(h));
    }
    if (i < 3 * 64 * 320) {
        int l = i / (64 * 320), r = i % (64 * 320);
        int n = r / 320, k = r % 320;
        float v = wr[(size_t)l * 320 * 64 + (size_t)k * 64 + n];
        __nv_bfloat16 h = __float2bfloat16_rn(v);
        g_WR[((size_t)(l * 2 + 0) * 64 + n) * 320 + k] = h;
        g_WR[((size_t)(l * 2 + 1) * 64 + n) * 320 + k] =
            __float2bfloat16_rn(v - __bfloat162float(h));
    }
}

// ---------------------------------------------------------------------------
// smem layout (bytes)
// ---------------------------------------------------------------------------
constexpr int OFF_IDX = 0;            // 128 x int4 = 2048
constexpr int OFF_BIAS = 2048, OFF_G = 2304, OFF_LB = 2560;
constexpr int OFF_C1 = 2816;          // 64x32 f32 = 8192 (CLS only)
constexpr int OFF_B1 = 11008, OFF_C2 = 11136;
constexpr int OFF_A = 11264;          // 1024-aligned
__host__ __device__ constexpr int ntmax(int C) { return (C == 64) ? 2 : 1; }
__host__ __device__ constexpr int off_b(int C) { return OFF_A + ntmax(C) * 2 * 16384; }
__host__ __device__ constexpr int smem_sz(int C) { return off_b(C) + ntmax(C) * 2 * 8192; }

// ---------------------------------------------------------------------------
// fused mesh-conv layer on mma.sync HMMA (split-bf16, 3-term)
// ---------------------------------------------------------------------------
template <int C, bool RESID, bool CLS>
__global__ __launch_bounds__(256)
void mesh_hmma(const float* __restrict__ xin, const int* __restrict__ nbr,
               const __nv_bfloat16* __restrict__ Wt,   // [term][64][KT]
               const float* __restrict__ bias, const float* __restrict__ lng,
               const float* __restrict__ lnb,
               const float* __restrict__ cw1, const float* __restrict__ cb1,
               const float* __restrict__ cw2, const float* __restrict__ cb2,
               float* __restrict__ out)
{
    constexpr bool C64 = (C == 64);
    constexpr int KT = C64 ? 320 : 64;
    constexpr int A_T = 16384, B_T = 8192;
    constexpr int OFF_BW = off_b(C);

    extern __shared__ char smc[];
    const int tid = threadIdx.x, wid = tid >> 5, lane = tid & 31;
    const int node0 = blockIdx.x * 128;

    auto At = [&](int t, int m) -> char* { return smc + OFF_A + (t * 2 + m) * A_T; };
    auto Bt = [&](int t, int m) -> char* { return smc + OFF_BW + (t * 2 + m) * B_T; };

    // ---- stage params, idx, classifier weights ----
    if (tid < 128) {
        int node = node0 + tid;
        int4 v = (node < E_NODES) ? ((const int4*)nbr)[node] : make_int4(0, 0, 0, 0);
        ((int4*)(smc + OFF_IDX))[tid] = v;
    }
    if (tid >= 128 && tid < 192) {
        int i = tid - 128;
        ((float*)(smc + OFF_BIAS))[i] = bias[i];
        ((float*)(smc + OFF_G))[i]    = lng[i];
        ((float*)(smc + OFF_LB))[i]   = lnb[i];
    }
    if (CLS) {
        for (int i = tid; i < 512; i += 256)
            ((float4*)(smc + OFF_C1))[i] = ((const float4*)cw1)[i];
        if (tid >= 192 && tid < 224) {
            int i = tid - 192;
            ((float*)(smc + OFF_B1))[i] = cb1[i];
            ((float*)(smc + OFF_C2))[i] = cw2[i];
        }
    }
    __syncthreads();

    const int  n      = tid >> 1;
    const int  half   = tid & 1;
    const bool vOK    = (node0 + n) < E_NODES;
    const int* sIdx   = (const int*)(smc + OFF_IDX);
    const int  R      = wid * 16;      // warp's output row strip

    float acc[8][4];
#pragma unroll
    for (int q = 0; q < 8; q++)
#pragma unroll
        for (int c = 0; c < 4; c++) acc[q][c] = 0.f;

    constexpr int NPH = C64 ? 3 : 1;
    for (int ph = 0; ph < NPH; ph++) {
        const int ntile = (C64 && ph > 0) ? 2 : 1;
        const int seg0  = (ph == 0) ? 0 : (ph == 1 ? 1 : 3);

        // ---- stage B tiles (pre-split, pre-transposed in global) ----
        for (int t = 0; t < ntile; t++)
            for (int term = 0; term < 2; term++) {
                const char* src = (const char*)(Wt + ((size_t)term * 64) * KT + (size_t)(seg0 + t) * 64);
                char* dst = Bt(t, term);
                for (int j = tid; j < 512; j += 256) {
                    int r = j >> 3, c = j & 7;
                    uint4 v = *(const uint4*)(src + (size_t)r * KT * 2 + c * 16);
                    *(uint4*)(dst + swz((u32)(r * 128 + c * 16))) = v;
                }
            }

        // ---- gather + split-convert A tiles ----
        if (vOK) {
            if (C64) {
                if (ph == 0) {
                    const float4* xr = (const float4*)(xin + (size_t)(node0 + n) * 64) + half * 8;
                    char* hT = At(0, 0); char* lT = At(0, 1);
#pragma unroll
                    for (int i = 0; i < 8; i++) {
                        float4 v = xr[i];
                        wr4(hT, lT, n, half * 32 + i * 4, v.x, v.y, v.z, v.w);
                    }
                } else {
                    const int ia = sIdx[4 * n + (ph == 1 ? 0 : 1)];
                    const int ic = sIdx[4 * n + (ph == 1 ? 2 : 3)];
                    const float4* ar = (const float4*)(xin + (size_t)ia * 64) + half * 8;
                    const float4* cr = (const float4*)(xin + (size_t)ic * 64) + half * 8;
                    char* hA = At(0, 0); char* lA = At(0, 1);
                    char* hS = At(1, 0); char* lS = At(1, 1);
#pragma unroll
                    for (int i = 0; i < 8; i++) {
                        float4 a = ar[i], c = cr[i];
                        int kc = half * 32 + i * 4;
                        wr4(hA, lA, n, kc, fabsf(a.x - c.x), fabsf(a.y - c.y),
                            fabsf(a.z - c.z), fabsf(a.w - c.w));
                        wr4(hS, lS, n, kc, a.x + c.x, a.y + c.y, a.z + c.z, a.w + c.w);
                    }
                }
            } else {
                // layer0: feats k map: x 0-10, |a-c| 11-21, a+c 22-32,
                // |b-d| 33-43, b+d 44-54, zero-pad 55-63
                char* hT = At(0, 0); char* lT = At(0, 1);
                if (half == 0) {
                    const float* xr = xin + (size_t)(node0 + n) * 11;
                    const float* A_ = xin + (size_t)sIdx[4 * n + 0] * 11;
                    const float* C_ = xin + (size_t)sIdx[4 * n + 2] * 11;
#pragma unroll
                    for (int ch = 0; ch < 11; ch++) {
                        wr1(hT, lT, n, ch, xr[ch]);
                        float a = A_[ch], c = C_[ch];
                        wr1(hT, lT, n, 11 + ch, fabsf(a - c));
                        wr1(hT, lT, n, 22 + ch, a + c);
                    }
                } else {
                    const float* B_ = xin + (size_t)sIdx[4 * n + 1] * 11;
                    const float* D_ = xin + (size_t)sIdx[4 * n + 3] * 11;
#pragma unroll
                    for (int ch = 0; ch < 11; ch++) {
                        float b = B_[ch], d = D_[ch];
                        wr1(hT, lT, n, 33 + ch, fabsf(b - d));
                        wr1(hT, lT, n, 44 + ch, b + d);
                    }
#pragma unroll
                    for (int k = 55; k < 64; k++) wr1(hT, lT, n, k, 0.f);
                }
            }
        }
        __syncthreads();

        // ---- warp-level HMMA over this phase's K tiles ----
        const int t4 = lane >> 3;
        for (int t = 0; t < ntile; t++) {
            const u32 ah_b = s2u(At(t, 0)), al_b = s2u(At(t, 1));
            const u32 bh_b = s2u(Bt(t, 0)), bl_b = s2u(Bt(t, 1));
#pragma unroll
            for (int k16 = 0; k16 < 4; k16++) {
                u32 aoff = swz((u32)((R + (lane & 7) + ((t4 & 1) << 3)) * 128
                                     + k16 * 32 + ((t4 >> 1) << 4)));
                u32 ah[4], al[4];
                ldmx4(ah, ah_b + aoff);
                ldmx4(al, al_b + aoff);
                u32 bh[16], bl[16];
#pragma unroll
                for (int p = 0; p < 4; p++) {
                    u32 boff = swz((u32)(((2 * p + (t4 >> 1)) * 8 + (lane & 7)) * 128
                                         + k16 * 32 + ((t4 & 1) << 4)));
                    ldmx4(bh + 4 * p, bh_b + boff);
                    ldmx4(bl + 4 * p, bl_b + boff);
                }
#pragma unroll
                for (int q = 0; q < 8; q++) {
                    mma16816(acc[q], ah, bh[2 * q], bh[2 * q + 1]);
                    mma16816(acc[q], al, bh[2 * q], bh[2 * q + 1]);
                    mma16816(acc[q], ah, bl[2 * q], bl[2 * q + 1]);
                }
            }
        }
        __syncthreads();
    }

    // ---- store acc tile into smem C (stride 65), reusing A/B region ----
    float* sC = (float*)(smc + OFF_A);
    {
        int r0 = R + (lane >> 2);
        int c0 = 2 * (lane & 3);
#pragma unroll
        for (int q = 0; q < 8; q++) {
            sC[r0 * 65 + q * 8 + c0]           = acc[q][0];
            sC[r0 * 65 + q * 8 + c0 + 1]       = acc[q][1];
            sC[(r0 + 8) * 65 + q * 8 + c0]     = acc[q][2];
            sC[(r0 + 8) * 65 + q * 8 + c0 + 1] = acc[q][3];
        }
    }
    __syncthreads();

    // ---- bias + LayerNorm + ReLU (one thread per node row) ----
    const float* sBias = (const float*)(smc + OFF_BIAS);
    const float* sG    = (const float*)(smc + OFF_G);
    const float* sB    = (const float*)(smc + OFF_LB);
    if (tid < 128 && (node0 + tid) < E_NODES) {
        const int row = tid;
        float mu = 0.f;
        for (int i = 0; i < 64; i++) mu += sC[row * 65 + i] + sBias[i];
        mu *= (1.f / 64.f);
        float var = 0.f;
        for (int i = 0; i < 64; i++) {
            float d = sC[row * 65 + i] + sBias[i] - mu;
            var += d * d;
        }
        var *= (1.f / 64.f);
        float rs = rsqrtf(var + 1e-5f);
        for (int i = 0; i < 64; i++) {
            float y = (sC[row * 65 + i] + sBias[i] - mu) * rs * sG[i] + sB[i];
            sC[row * 65 + i] = fmaxf(y, 0.f);
        }
    }
    __syncthreads();

    if (!CLS) {
        // residual + coalesced store (2 threads per node, float4)
        if (vOK) {
            const int node = node0 + n;
            float4* orow = (float4*)(out + (size_t)node * 64) + half * 8;
            const float4* xr = RESID ? ((const float4*)(xin + (size_t)node * 64) + half * 8)
                                     : (const float4*)0;
#pragma unroll
            for (int i = 0; i < 8; i++) {
                int c0 = half * 32 + i * 4;
                float4 r;
                r.x = sC[n * 65 + c0 + 0];
                r.y = sC[n * 65 + c0 + 1];
                r.z = sC[n * 65 + c0 + 2];
                r.w = sC[n * 65 + c0 + 3];
                if (RESID) {
                    float4 x4 = xr[i];
                    r.x += x4.x; r.y += x4.y; r.z += x4.z; r.w += x4.w;
                }
                orow[i] = r;
            }
        }
    } else {
        // residual add into smem, then fused classifier head
        if (RESID && vOK) {
            const float4* xr = (const float4*)(xin + (size_t)(node0 + n) * 64) + half * 8;
#pragma unroll
            for (int i = 0; i < 8; i++) {
                float4 x4 = xr[i];
                int c0 = half * 32 + i * 4;
                sC[n * 65 + c0 + 0] += x4.x;
                sC[n * 65 + c0 + 1] += x4.y;
                sC[n * 65 + c0 + 2] += x4.z;
                sC[n * 65 + c0 + 3] += x4.w;
            }
        }
        __syncthreads();
        if (tid < 128 && (node0 + tid) < E_NODES) {
            const int row = tid;
            const u64* zb = (const u64*)(smc + OFF_B1);
            u64 z[16];
#pragma unroll
            for (int j = 0; j < 16; j++) z[j] = zb[j];
            for (int i = 0; i < 64; i++) {
                float vi = sC[row * 65 + i];
                u64 v2 = pk2(vi, vi);
                const u64* wrow = (const u64*)(smc + OFF_C1 + i * 128);
#pragma unroll
                for (int j = 0; j < 16; j++) ffma2(z[j], v2, wrow[j]);
            }
            const float* sC2 = (const float*)(smc + OFF_C2);
            float logit = __ldg(cb2);
#pragma unroll
            for (int j = 0; j < 16; j++) {
                float lo, hi;
                upk2(z[j], lo, hi);
                logit += fmaxf(lo, 0.f) * sC2[2 * j] + fmaxf(hi, 0.f) * sC2[2 * j + 1];
            }
            out[node0 + row] = logit;
        }
    }
}

// ---------------------------------------------------------------------------

extern "C" void kernel_launch(void* const* d_in, const int* in_sizes, int n_in,
                              void* d_out, int out_size)
{
    const float* x      = (const float*)d_in[0];
    const int*   nbr    = (const int*)  d_in[1];
    const float* w0     = (const float*)d_in[2];
    const float* b0     = (const float*)d_in[3];
    const float* w_rest = (const float*)d_in[4];
    const float* b_rest = (const float*)d_in[5];
    const float* ln_g   = (const float*)d_in[6];
    const float* ln_b   = (const float*)d_in[7];
    const float* cw1    = (const float*)d_in[8];
    const float* cb1    = (const float*)d_in[9];
    const float* cw2    = (const float*)d_in[10];
    const float* cb2    = (const float*)d_in[11];
    float* out = (float*)d_out;

    float *bufA, *bufB;
    __nv_bfloat16 *W0p, *WRp;
    cudaGetSymbolAddress((void**)&bufA, g_bufA);
    cudaGetSymbolAddress((void**)&bufB, g_bufB);
    cudaGetSymbolAddress((void**)&W0p, g_W0);
    cudaGetSymbolAddress((void**)&WRp, g_WR);

    const int s11 = smem_sz(11);
    const int s64 = smem_sz(64);

    cudaFuncSetAttribute(mesh_hmma<11, false, false>,
                         cudaFuncAttributeMaxDynamicSharedMemorySize, s11);
    cudaFuncSetAttribute(mesh_hmma<64, true, false>,
                         cudaFuncAttributeMaxDynamicSharedMemorySize, s64);
    cudaFuncSetAttribute(mesh_hmma<64, true, true>,
                         cudaFuncAttributeMaxDynamicSharedMemorySize, s64);

    prep_w<<<240, 256>>>(w0, w_rest);

    dim3 grid((E_NODES + 127) / 128);
    dim3 block(256);

    mesh_hmma<11, false, false><<<grid, block, s11>>>(
        x, nbr, W0p, b0, ln_g, ln_b,
        nullptr, nullptr, nullptr, nullptr, bufA);

    mesh_hmma<64, true, false><<<grid, block, s64>>>(
        bufA, nbr, WRp, b_rest, ln_g + 64, ln_b + 64,
        nullptr, nullptr, nullptr, nullptr, bufB);

    mesh_hmma<64, true, false><<<grid, block, s64>>>(
        bufB, nbr, WRp + 2 * 64 * 320, b_rest + 64, ln_g + 128, ln_b + 128,
        nullptr, nullptr, nullptr, nullptr, bufA);

    mesh_hmma<64, true, true><<<grid, block, s64>>>(
        bufA, nbr, WRp + 4 * 64 * 320, b_rest + 128, ln_g + 192, ln_b + 192,
        cw1, cb1, cw2, cb2, out);
}